// round 10
// baseline (speedup 1.0000x reference)
#include <cuda_runtime.h>
#include <cuda_bf16.h>
#include <cstdint>

#define H      128
#define NH     8
#define HDIM   16
#define MAXDEG 16
#define MAXN_PAD 50048      // 391 * 128, >= N

// ---------------- scratch (device globals: no allocations allowed) ----------
// Q, K stored PERMUTED: feature f = d*8+hd  ->  slot hd*16+d  (head-contiguous)
// V stored in original layout. g_ATT holds softmaxed weights [node][hd*16+e].
__device__ __align__(16) float g_Q[MAXN_PAD * H];
__device__ __align__(16) float g_K[MAXN_PAD * H];
__device__ __align__(16) float g_V[MAXN_PAD * H];
__device__ __align__(16) float g_ATT[MAXN_PAD * H];

// ---------------- packed f32x2 helpers --------------------------------------
__device__ __forceinline__ unsigned long long fma2(unsigned long long a,
                                                   unsigned long long b,
                                                   unsigned long long c) {
    unsigned long long d;
    asm("fma.rn.f32x2 %0, %1, %2, %3;" : "=l"(d) : "l"(a), "l"(b), "l"(c));
    return d;
}
__device__ __forceinline__ unsigned long long dup2(float x) {
    unsigned long long r;
    unsigned int xi = __float_as_uint(x);
    asm("mov.b64 %0, {%1, %1};" : "=l"(r) : "r"(xi));
    return r;
}
__device__ __forceinline__ void unpack2(unsigned long long v, float& lo, float& hi) {
    unsigned int a, b;
    asm("mov.b64 {%0, %1}, %2;" : "=r"(a), "=r"(b) : "l"(v));
    lo = __uint_as_float(a);
    hi = __uint_as_float(b);
}

// ---------------- projection GEMM (exact R6 mainloop: 121us measured) -------
// z = blockIdx.z + zoff: 0 -> Q (scale 0.25, permuted), 1 -> K (permuted), 2 -> V.
// 128x128 tile, BK=32, 256 threads, 8x8 microtile, f32x2 FMA, reg prefetch.
__global__ __launch_bounds__(256, 2) void qkv_gemm(
    const float* __restrict__ hmat,
    const float* __restrict__ Wq, const float* __restrict__ bq,
    const float* __restrict__ Wk, const float* __restrict__ bk,
    const float* __restrict__ Wv, const float* __restrict__ bv,
    int N, int zoff)
{
    const int z = blockIdx.z + zoff;
    const float* __restrict__ W    = (z == 0) ? Wq : (z == 1) ? Wk : Wv;
    const float* __restrict__ bias = (z == 0) ? bq : (z == 1) ? bk : bv;
    float* __restrict__ C          = (z == 0) ? g_Q : (z == 1) ? g_K : g_V;
    const float scale   = (z == 0) ? 0.25f : 1.0f;   // head_dim^-0.5 = 16^-0.5
    const bool  permute = (z < 2);

    __shared__ __align__(16) float As[32][132];    // [k][m]
    __shared__ __align__(16) float Bs[32][132];    // [k][n]

    const int tid  = threadIdx.x;
    const int row0 = blockIdx.x * 128;
    const int sr   = tid >> 1;               // staging row 0..127
    const int sc   = (tid & 1) * 16;         // staging col base 0 or 16
    const int tx   = tid & 15;               // n-tile 0..15
    const int ty   = tid >> 4;               // m-tile 0..15
    const bool arow_ok = (row0 + sr < N);

    unsigned long long acc[8][4];
#pragma unroll
    for (int i = 0; i < 8; i++)
#pragma unroll
        for (int j = 0; j < 4; j++) acc[i][j] = 0ULL;

    // prefetch chunk 0
    float4 av[4], wv[4];
#pragma unroll
    for (int i = 0; i < 4; i++) {
        av[i] = arow_ok
            ? *reinterpret_cast<const float4*>(hmat + (size_t)(row0 + sr) * H + sc + i * 4)
            : make_float4(0.f, 0.f, 0.f, 0.f);
        wv[i] = *reinterpret_cast<const float4*>(W + (size_t)sr * H + sc + i * 4);
    }

    for (int chunk = 0; chunk < 4; chunk++) {
#pragma unroll
        for (int i = 0; i < 4; i++) {
            int k0 = sc + i * 4;
            As[k0 + 0][sr] = av[i].x; As[k0 + 1][sr] = av[i].y;
            As[k0 + 2][sr] = av[i].z; As[k0 + 3][sr] = av[i].w;
            Bs[k0 + 0][sr] = wv[i].x; Bs[k0 + 1][sr] = wv[i].y;
            Bs[k0 + 2][sr] = wv[i].z; Bs[k0 + 3][sr] = wv[i].w;
        }
        __syncthreads();

        if (chunk < 3) {
            int kk = (chunk + 1) * 32;
#pragma unroll
            for (int i = 0; i < 4; i++) {
                av[i] = arow_ok
                    ? *reinterpret_cast<const float4*>(hmat + (size_t)(row0 + sr) * H + kk + sc + i * 4)
                    : make_float4(0.f, 0.f, 0.f, 0.f);
                wv[i] = *reinterpret_cast<const float4*>(W + (size_t)sr * H + kk + sc + i * 4);
            }
        }

#pragma unroll 8
        for (int k = 0; k < 32; k++) {
            ulonglong2 b01 = *reinterpret_cast<const ulonglong2*>(&Bs[k][tx * 8]);
            ulonglong2 b23 = *reinterpret_cast<const ulonglong2*>(&Bs[k][tx * 8 + 4]);
            float4 a0 = *reinterpret_cast<const float4*>(&As[k][ty * 8]);
            float4 a1 = *reinterpret_cast<const float4*>(&As[k][ty * 8 + 4]);
            unsigned long long ad[8];
            ad[0] = dup2(a0.x); ad[1] = dup2(a0.y); ad[2] = dup2(a0.z); ad[3] = dup2(a0.w);
            ad[4] = dup2(a1.x); ad[5] = dup2(a1.y); ad[6] = dup2(a1.z); ad[7] = dup2(a1.w);
#pragma unroll
            for (int i = 0; i < 8; i++) {
                acc[i][0] = fma2(ad[i], b01.x, acc[i][0]);
                acc[i][1] = fma2(ad[i], b01.y, acc[i][1]);
                acc[i][2] = fma2(ad[i], b23.x, acc[i][2]);
                acc[i][3] = fma2(ad[i], b23.y, acc[i][3]);
            }
        }
        __syncthreads();
    }

    // epilogue: bias + scale + (optional) head-permute store
    float bl[8];
#pragma unroll
    for (int u = 0; u < 8; u++) bl[u] = __ldg(bias + tx * 8 + u);

#pragma unroll
    for (int i = 0; i < 8; i++) {
        int gr = row0 + ty * 8 + i;
        if (gr >= N) continue;
        float vals[8];
#pragma unroll
        for (int j = 0; j < 4; j++) {
            float lo, hi;
            unpack2(acc[i][j], lo, hi);
            vals[2 * j]     = (lo + bl[2 * j])     * scale;
            vals[2 * j + 1] = (hi + bl[2 * j + 1]) * scale;
        }
        float* crow = C + (size_t)gr * H;
        if (permute) {
            // c = tx*8+u -> slot (c&7)*16 + (c>>3) = u*16 + tx
#pragma unroll
            for (int u = 0; u < 8; u++) crow[u * 16 + tx] = vals[u];
        } else {
            *reinterpret_cast<float4*>(crow + tx * 8) =
                make_float4(vals[0], vals[1], vals[2], vals[3]);
            *reinterpret_cast<float4*>(crow + tx * 8 + 4) =
                make_float4(vals[4], vals[5], vals[6], vals[7]);
        }
    }
}

// ---------------- score + softmax kernel (needs Q, K only) ------------------
// One warp per node. Writes softmaxed weights to g_ATT[node][hd*16+e].
__global__ __launch_bounds__(256) void score_kernel(
    const int* __restrict__ row_ptr,
    const int* __restrict__ col_ind,
    int N)
{
    const int lane = threadIdx.x & 31;
    const int node = blockIdx.x * 8 + (threadIdx.x >> 5);
    if (node >= N) return;

    const int start = row_ptr[node];
    int deg = row_ptr[node + 1] - start;
    if (deg > MAXDEG) deg = MAXDEG;

    int colv = 0;
    if (lane < MAXDEG && lane < deg) colv = col_ind[start + lane];

    const float4 q4 = *reinterpret_cast<const float4*>(g_Q + (size_t)node * H + lane * 4);

    const float NEG_INF = __int_as_float(0xff800000);
    float sc[MAXDEG];
#pragma unroll
    for (int e = 0; e < MAXDEG; e++) {
        int col = __shfl_sync(0xffffffffu, colv, e);
        float4 k4 = __ldg(reinterpret_cast<const float4*>(g_K + (size_t)col * H) + lane);
        float p = q4.x * k4.x + q4.y * k4.y + q4.z * k4.z + q4.w * k4.w;
        p += __shfl_xor_sync(0xffffffffu, p, 1);
        p += __shfl_xor_sync(0xffffffffu, p, 2);   // quad = 16 d's of head lane>>2
        sc[e] = (e < deg) ? p : NEG_INF;
    }

    float m = NEG_INF;
#pragma unroll
    for (int e = 0; e < MAXDEG; e++) m = fmaxf(m, sc[e]);
    float s = 0.0f;
#pragma unroll
    for (int e = 0; e < MAXDEG; e++) { float x = __expf(sc[e] - m); sc[e] = x; s += x; }
    float r = __frcp_rn(s);
#pragma unroll
    for (int e = 0; e < MAXDEG; e++) sc[e] *= r;

    // lane (hd = lane>>2) owns edges e0..e0+3: store [hd*16+e] layout, coalesced
    const int hd = lane >> 2;
    const int e0 = (lane & 3) * 4;
    *reinterpret_cast<float4*>(g_ATT + (size_t)node * H + hd * MAXDEG + e0) =
        make_float4(sc[e0], sc[e0 + 1], sc[e0 + 2], sc[e0 + 3]);
}

// ---------------- V-accumulate kernel (needs V + g_ATT) ---------------------
__global__ __launch_bounds__(256) void vpass_kernel(
    const int* __restrict__ row_ptr,
    const int* __restrict__ col_ind,
    float* __restrict__ out,
    int N)
{
    __shared__ float att[8][H];   // [local warp][hd*16+e]

    const int wl   = threadIdx.x >> 5;
    const int lane = threadIdx.x & 31;
    const int node = blockIdx.x * 8 + wl;
    if (node >= N) return;

    const int start = row_ptr[node];
    int deg = row_ptr[node + 1] - start;
    if (deg > MAXDEG) deg = MAXDEG;

    int colv = 0;
    if (lane < MAXDEG && lane < deg) colv = col_ind[start + lane];

    *reinterpret_cast<float4*>(&att[wl][lane * 4]) =
        *reinterpret_cast<const float4*>(g_ATT + (size_t)node * H + lane * 4);
    __syncwarp();

    // feature f = 4*lane+j -> head base+j, base = 4*(lane&1); padded edges weight 0
    const int base = (lane & 1) * 4;
    float4 acc = make_float4(0.f, 0.f, 0.f, 0.f);
#pragma unroll
    for (int e = 0; e < MAXDEG; e++) {
        int col = __shfl_sync(0xffffffffu, colv, e);
        float4 v4 = __ldg(reinterpret_cast<const float4*>(g_V + (size_t)col * H) + lane);
        acc.x += att[wl][(base + 0) * MAXDEG + e] * v4.x;
        acc.y += att[wl][(base + 1) * MAXDEG + e] * v4.y;
        acc.z += att[wl][(base + 2) * MAXDEG + e] * v4.z;
        acc.w += att[wl][(base + 3) * MAXDEG + e] * v4.w;
    }
    *reinterpret_cast<float4*>(out + (size_t)node * H + lane * 4) = acc;
}

// ---------------- launch: proper fork-join on non-blocking streams ----------
// Branches live on s2 (V-GEMM) and s3 (score) — NEVER on the legacy stream,
// whose implicit-sync semantics serialized the R9 fork. Only QK-GEMM and the
// join + vpass run on the capture stream (stream 0 as seen here).
extern "C" void kernel_launch(void* const* d_in, const int* in_sizes, int n_in,
                              void* d_out, int out_size) {
    const float* h   = (const float*)d_in[0];
    const float* Wq  = (const float*)d_in[1];
    const float* bq  = (const float*)d_in[2];
    const float* Wk  = (const float*)d_in[3];
    const float* bk  = (const float*)d_in[4];
    const float* Wv  = (const float*)d_in[5];
    const float* bv  = (const float*)d_in[6];
    const int* row_ptr = (const int*)d_in[7];
    const int* col_ind = (const int*)d_in[8];
    float* out = (float*)d_out;

    const int N = in_sizes[0] / H;
    const int gblocks = (N + 127) / 128;
    const int ablocks = (N + 7) / 8;

    static cudaStream_t s2 = nullptr, s3 = nullptr;
    static cudaEvent_t ev_fork = nullptr, ev_j2 = nullptr, ev_j3 = nullptr;
    if (s2 == nullptr) {
        cudaStreamCreateWithFlags(&s2, cudaStreamNonBlocking);
        cudaStreamCreateWithFlags(&s3, cudaStreamNonBlocking);
        cudaEventCreateWithFlags(&ev_fork, cudaEventDisableTiming);
        cudaEventCreateWithFlags(&ev_j2, cudaEventDisableTiming);
        cudaEventCreateWithFlags(&ev_j3, cudaEventDisableTiming);
    }

    // QK-GEMM on the capture stream
    qkv_gemm<<<dim3(gblocks, 1, 2), 256>>>(h, Wq, bq, Wk, bk, Wv, bv, N, 0);
    cudaEventRecord(ev_fork, 0);

    // branch A: V-GEMM on s2
    cudaStreamWaitEvent(s2, ev_fork, 0);
    qkv_gemm<<<dim3(gblocks, 1, 1), 256, 0, s2>>>(h, Wq, bq, Wk, bk, Wv, bv, N, 2);
    cudaEventRecord(ev_j2, s2);

    // branch B: score+softmax on s3 (concurrent with V-GEMM)
    cudaStreamWaitEvent(s3, ev_fork, 0);
    score_kernel<<<ablocks, 256, 0, s3>>>(row_ptr, col_ind, N);
    cudaEventRecord(ev_j3, s3);

    // join both branches into the capture stream, then vpass
    cudaStreamWaitEvent(0, ev_j2, 0);
    cudaStreamWaitEvent(0, ev_j3, 0);
    vpass_kernel<<<ablocks, 256>>>(row_ptr, col_ind, out, N);
}

// round 11
// speedup vs baseline: 1.2135x; 1.2135x over previous
#include <cuda_runtime.h>
#include <cuda_fp16.h>
#include <cstdint>

#define H      128
#define NH     8
#define HDIM   16
#define MAXDEG 16
#define MAXN_PAD 50048      // 391 * 128, >= N

// ---------------- scratch (device globals: no allocations allowed) ----------
// Q fp32, PERMUTED: feature f = d*8+hd -> slot hd*16+d (head-contiguous).
// K fp16, PERMUTED same layout.  V fp16, ORIGINAL layout.
__device__ __align__(16) float  g_Q[MAXN_PAD * H];
__device__ __align__(16) __half g_K[MAXN_PAD * H];
__device__ __align__(16) __half g_V[MAXN_PAD * H];

// ---------------- packed f32x2 helpers --------------------------------------
__device__ __forceinline__ unsigned long long fma2(unsigned long long a,
                                                   unsigned long long b,
                                                   unsigned long long c) {
    unsigned long long d;
    asm("fma.rn.f32x2 %0, %1, %2, %3;" : "=l"(d) : "l"(a), "l"(b), "l"(c));
    return d;
}
__device__ __forceinline__ unsigned long long dup2(float x) {
    unsigned long long r;
    unsigned int xi = __float_as_uint(x);
    asm("mov.b64 %0, {%1, %1};" : "=l"(r) : "r"(xi));
    return r;
}
__device__ __forceinline__ void unpack2(unsigned long long v, float& lo, float& hi) {
    unsigned int a, b;
    asm("mov.b64 {%0, %1}, %2;" : "=r"(a), "=r"(b) : "l"(v));
    lo = __uint_as_float(a);
    hi = __uint_as_float(b);
}

// ---------------- QKV projection: C = h @ W^T + b (x scale for Q) -----------
// Exact R6 mainloop (121us measured). blockIdx.z: 0->Q fp32 perm, 1->K fp16
// perm, 2->V fp16 original. 128x128 tile, BK=32, 256 thr, 8x8 microtile.
__global__ __launch_bounds__(256, 2) void qkv_gemm(
    const float* __restrict__ hmat,
    const float* __restrict__ Wq, const float* __restrict__ bq,
    const float* __restrict__ Wk, const float* __restrict__ bk,
    const float* __restrict__ Wv, const float* __restrict__ bv,
    int N)
{
    const int z = blockIdx.z;
    const float* __restrict__ W    = (z == 0) ? Wq : (z == 1) ? Wk : Wv;
    const float* __restrict__ bias = (z == 0) ? bq : (z == 1) ? bk : bv;
    const float scale = (z == 0) ? 0.25f : 1.0f;   // head_dim^-0.5 = 16^-0.5

    __shared__ __align__(16) float As[32][132];    // [k][m]
    __shared__ __align__(16) float Bs[32][132];    // [k][n]

    const int tid  = threadIdx.x;
    const int row0 = blockIdx.x * 128;
    const int sr   = tid >> 1;               // staging row 0..127
    const int sc   = (tid & 1) * 16;         // staging col base 0 or 16
    const int tx   = tid & 15;               // n-tile 0..15
    const int ty   = tid >> 4;               // m-tile 0..15
    const bool arow_ok = (row0 + sr < N);

    unsigned long long acc[8][4];
#pragma unroll
    for (int i = 0; i < 8; i++)
#pragma unroll
        for (int j = 0; j < 4; j++) acc[i][j] = 0ULL;

    // prefetch chunk 0
    float4 av[4], wv[4];
#pragma unroll
    for (int i = 0; i < 4; i++) {
        av[i] = arow_ok
            ? *reinterpret_cast<const float4*>(hmat + (size_t)(row0 + sr) * H + sc + i * 4)
            : make_float4(0.f, 0.f, 0.f, 0.f);
        wv[i] = *reinterpret_cast<const float4*>(W + (size_t)sr * H + sc + i * 4);
    }

    for (int chunk = 0; chunk < 4; chunk++) {
#pragma unroll
        for (int i = 0; i < 4; i++) {
            int k0 = sc + i * 4;
            As[k0 + 0][sr] = av[i].x; As[k0 + 1][sr] = av[i].y;
            As[k0 + 2][sr] = av[i].z; As[k0 + 3][sr] = av[i].w;
            Bs[k0 + 0][sr] = wv[i].x; Bs[k0 + 1][sr] = wv[i].y;
            Bs[k0 + 2][sr] = wv[i].z; Bs[k0 + 3][sr] = wv[i].w;
        }
        __syncthreads();

        if (chunk < 3) {
            int kk = (chunk + 1) * 32;
#pragma unroll
            for (int i = 0; i < 4; i++) {
                av[i] = arow_ok
                    ? *reinterpret_cast<const float4*>(hmat + (size_t)(row0 + sr) * H + kk + sc + i * 4)
                    : make_float4(0.f, 0.f, 0.f, 0.f);
                wv[i] = *reinterpret_cast<const float4*>(W + (size_t)sr * H + kk + sc + i * 4);
            }
        }

#pragma unroll 8
        for (int k = 0; k < 32; k++) {
            ulonglong2 b01 = *reinterpret_cast<const ulonglong2*>(&Bs[k][tx * 8]);
            ulonglong2 b23 = *reinterpret_cast<const ulonglong2*>(&Bs[k][tx * 8 + 4]);
            float4 a0 = *reinterpret_cast<const float4*>(&As[k][ty * 8]);
            float4 a1 = *reinterpret_cast<const float4*>(&As[k][ty * 8 + 4]);
            unsigned long long ad[8];
            ad[0] = dup2(a0.x); ad[1] = dup2(a0.y); ad[2] = dup2(a0.z); ad[3] = dup2(a0.w);
            ad[4] = dup2(a1.x); ad[5] = dup2(a1.y); ad[6] = dup2(a1.z); ad[7] = dup2(a1.w);
#pragma unroll
            for (int i = 0; i < 8; i++) {
                acc[i][0] = fma2(ad[i], b01.x, acc[i][0]);
                acc[i][1] = fma2(ad[i], b01.y, acc[i][1]);
                acc[i][2] = fma2(ad[i], b23.x, acc[i][2]);
                acc[i][3] = fma2(ad[i], b23.y, acc[i][3]);
            }
        }
        __syncthreads();
    }

    // epilogue: bias + scale, then per-z store (fp32 perm / fp16 perm / fp16)
    float bl[8];
#pragma unroll
    for (int u = 0; u < 8; u++) bl[u] = __ldg(bias + tx * 8 + u);

#pragma unroll
    for (int i = 0; i < 8; i++) {
        int gr = row0 + ty * 8 + i;
        if (gr >= N) continue;
        float vals[8];
#pragma unroll
        for (int j = 0; j < 4; j++) {
            float lo, hi;
            unpack2(acc[i][j], lo, hi);
            vals[2 * j]     = (lo + bl[2 * j])     * scale;
            vals[2 * j + 1] = (hi + bl[2 * j + 1]) * scale;
        }
        if (z == 0) {
            // Q fp32, permuted: c = tx*8+u -> slot (c&7)*16 + (c>>3) = u*16 + tx
            float* crow = g_Q + (size_t)gr * H;
#pragma unroll
            for (int u = 0; u < 8; u++) crow[u * 16 + tx] = vals[u];
        } else if (z == 1) {
            // K fp16, permuted
            __half* crow = g_K + (size_t)gr * H;
#pragma unroll
            for (int u = 0; u < 8; u++) crow[u * 16 + tx] = __float2half_rn(vals[u]);
        } else {
            // V fp16, original layout: 8 halves = 16B contiguous
            __half hv[8];
#pragma unroll
            for (int u = 0; u < 8; u++) hv[u] = __float2half_rn(vals[u]);
            *reinterpret_cast<uint4*>(g_V + (size_t)gr * H + tx * 8) =
                *reinterpret_cast<const uint4*>(hv);
        }
    }
}

// ---------------- fused sparse attention: one warp per node -----------------
// Q fp32 permuted; K fp16 permuted; V fp16 original.
// Score pass: lane owns slots p=4*lane..4*lane+3 -> head lane>>2 (quad-reduce).
// V pass: lane owns features f=4*lane..4*lane+3 -> head 4*(lane&1)+j.
__global__ __launch_bounds__(256) void attn_kernel(
    const int* __restrict__ row_ptr,
    const int* __restrict__ col_ind,
    float* __restrict__ out,
    int N)
{
    __shared__ float att[8][NH][MAXDEG];   // [local warp][head][edge]

    const int wl   = threadIdx.x >> 5;
    const int lane = threadIdx.x & 31;
    const int node = blockIdx.x * 8 + wl;
    if (node >= N) return;                 // warp-uniform; only __syncwarp below

    const int start = row_ptr[node];
    int deg = row_ptr[node + 1] - start;
    if (deg > MAXDEG) deg = MAXDEG;

    int colv = 0;
    if (lane < MAXDEG && lane < deg) colv = col_ind[start + lane];

    const float4 q4 = *reinterpret_cast<const float4*>(g_Q + (size_t)node * H + lane * 4);

    const float NEG_INF = __int_as_float(0xff800000);
    float sc[MAXDEG];
#pragma unroll
    for (int e = 0; e < MAXDEG; e++) {
        int col = __shfl_sync(0xffffffffu, colv, e);
        uint2 kr = __ldg(reinterpret_cast<const uint2*>(g_K + (size_t)col * H) + lane);
        float2 k01 = __half22float2(*reinterpret_cast<const __half2*>(&kr.x));
        float2 k23 = __half22float2(*reinterpret_cast<const __half2*>(&kr.y));
        float p = q4.x * k01.x + q4.y * k01.y + q4.z * k23.x + q4.w * k23.y;
        p += __shfl_xor_sync(0xffffffffu, p, 1);
        p += __shfl_xor_sync(0xffffffffu, p, 2);   // quad = 16 d's of head lane>>2
        sc[e] = (e < deg) ? p : NEG_INF;
    }

    // per-lane softmax over edges (all 4 lanes of a quad hold identical copies)
    float m = NEG_INF;
#pragma unroll
    for (int e = 0; e < MAXDEG; e++) m = fmaxf(m, sc[e]);
    float s = 0.0f;
#pragma unroll
    for (int e = 0; e < MAXDEG; e++) { float x = __expf(sc[e] - m); sc[e] = x; s += x; }
    float r = __frcp_rn(s);
#pragma unroll
    for (int e = 0; e < MAXDEG; e++) sc[e] *= r;

    // transpose attn to smem: lane (hd = lane>>2) stores edges e0..e0+3
    {
        int hd = lane >> 2;
        int e0 = (lane & 3) * 4;
        *reinterpret_cast<float4*>(&att[wl][hd][e0]) =
            make_float4(sc[e0], sc[e0 + 1], sc[e0 + 2], sc[e0 + 3]);
    }
    __syncwarp();

    // bspmm: coalesced fp16 V rows, feature f = 4*lane+j -> head 4*(lane&1)+j
    const int base = (lane & 1) * 4;
    float4 acc = make_float4(0.f, 0.f, 0.f, 0.f);
#pragma unroll
    for (int e = 0; e < MAXDEG; e++) {
        int col = __shfl_sync(0xffffffffu, colv, e);
        uint2 vr = __ldg(reinterpret_cast<const uint2*>(g_V + (size_t)col * H) + lane);
        float2 v01 = __half22float2(*reinterpret_cast<const __half2*>(&vr.x));
        float2 v23 = __half22float2(*reinterpret_cast<const __half2*>(&vr.y));
        acc.x += att[wl][base + 0][e] * v01.x;
        acc.y += att[wl][base + 1][e] * v01.y;
        acc.z += att[wl][base + 2][e] * v23.x;
        acc.w += att[wl][base + 3][e] * v23.y;
    }
    *reinterpret_cast<float4*>(out + (size_t)node * H + lane * 4) = acc;
}

// ---------------- launch -----------------------------------------------------
extern "C" void kernel_launch(void* const* d_in, const int* in_sizes, int n_in,
                              void* d_out, int out_size) {
    const float* h   = (const float*)d_in[0];
    const float* Wq  = (const float*)d_in[1];
    const float* bq  = (const float*)d_in[2];
    const float* Wk  = (const float*)d_in[3];
    const float* bk  = (const float*)d_in[4];
    const float* Wv  = (const float*)d_in[5];
    const float* bv  = (const float*)d_in[6];
    const int* row_ptr = (const int*)d_in[7];
    const int* col_ind = (const int*)d_in[8];
    float* out = (float*)d_out;

    const int N = in_sizes[0] / H;

    dim3 ggrid((N + 127) / 128, 1, 3);
    qkv_gemm<<<ggrid, 256>>>(h, Wq, bq, Wk, bk, Wv, bv, N);

    const int ablocks = (N + 7) / 8;       // 8 nodes (warps) per 256-thread block
    attn_kernel<<<ablocks, 256>>>(row_ptr, col_ind, out, N);
}

// round 12
// speedup vs baseline: 1.2142x; 1.0006x over previous
#include <cuda_runtime.h>
#include <cuda_fp16.h>
#include <cstdint>

#define H      128
#define NH     8
#define HDIM   16
#define MAXDEG 16
#define MAXN_PAD 50048      // 391 * 128, >= N

// ---------------- scratch (device globals: no allocations allowed) ----------
// Q fp32, PERMUTED: feature f = d*8+hd -> slot hd*16+d (head-contiguous).
// K fp16, PERMUTED same layout.  V fp16, ORIGINAL layout.
__device__ __align__(16) float  g_Q[MAXN_PAD * H];
__device__ __align__(16) __half g_K[MAXN_PAD * H];
__device__ __align__(16) __half g_V[MAXN_PAD * H];

// ---------------- packed f32x2 helpers --------------------------------------
__device__ __forceinline__ unsigned long long fma2(unsigned long long a,
                                                   unsigned long long b,
                                                   unsigned long long c) {
    unsigned long long d;
    asm("fma.rn.f32x2 %0, %1, %2, %3;" : "=l"(d) : "l"(a), "l"(b), "l"(c));
    return d;
}
__device__ __forceinline__ unsigned long long dup2(float x) {
    unsigned long long r;
    unsigned int xi = __float_as_uint(x);
    asm("mov.b64 %0, {%1, %1};" : "=l"(r) : "r"(xi));
    return r;
}
__device__ __forceinline__ void unpack2(unsigned long long v, float& lo, float& hi) {
    unsigned int a, b;
    asm("mov.b64 {%0, %1}, %2;" : "=r"(a), "=r"(b) : "l"(v));
    lo = __uint_as_float(a);
    hi = __uint_as_float(b);
}

// ---------------- QKV projection: C = h @ W^T + b (x scale for Q) -----------
// Exact R6 mainloop (fma-pipe bound, 94% of FFMA2 rt=3 floor). blockIdx.z:
// 0->Q fp32 perm, 1->K fp16 perm, 2->V fp16 original.
__global__ __launch_bounds__(256, 2) void qkv_gemm(
    const float* __restrict__ hmat,
    const float* __restrict__ Wq, const float* __restrict__ bq,
    const float* __restrict__ Wk, const float* __restrict__ bk,
    const float* __restrict__ Wv, const float* __restrict__ bv,
    int N)
{
    const int z = blockIdx.z;
    const float* __restrict__ W    = (z == 0) ? Wq : (z == 1) ? Wk : Wv;
    const float* __restrict__ bias = (z == 0) ? bq : (z == 1) ? bk : bv;
    const float scale = (z == 0) ? 0.25f : 1.0f;   // head_dim^-0.5 = 16^-0.5

    __shared__ __align__(16) float As[32][132];    // [k][m]
    __shared__ __align__(16) float Bs[32][132];    // [k][n]

    const int tid  = threadIdx.x;
    const int row0 = blockIdx.x * 128;
    const int sr   = tid >> 1;               // staging row 0..127
    const int sc   = (tid & 1) * 16;         // staging col base 0 or 16
    const int tx   = tid & 15;               // n-tile 0..15
    const int ty   = tid >> 4;               // m-tile 0..15
    const bool arow_ok = (row0 + sr < N);

    unsigned long long acc[8][4];
#pragma unroll
    for (int i = 0; i < 8; i++)
#pragma unroll
        for (int j = 0; j < 4; j++) acc[i][j] = 0ULL;

    // prefetch chunk 0
    float4 av[4], wv[4];
#pragma unroll
    for (int i = 0; i < 4; i++) {
        av[i] = arow_ok
            ? *reinterpret_cast<const float4*>(hmat + (size_t)(row0 + sr) * H + sc + i * 4)
            : make_float4(0.f, 0.f, 0.f, 0.f);
        wv[i] = *reinterpret_cast<const float4*>(W + (size_t)sr * H + sc + i * 4);
    }

    for (int chunk = 0; chunk < 4; chunk++) {
#pragma unroll
        for (int i = 0; i < 4; i++) {
            int k0 = sc + i * 4;
            As[k0 + 0][sr] = av[i].x; As[k0 + 1][sr] = av[i].y;
            As[k0 + 2][sr] = av[i].z; As[k0 + 3][sr] = av[i].w;
            Bs[k0 + 0][sr] = wv[i].x; Bs[k0 + 1][sr] = wv[i].y;
            Bs[k0 + 2][sr] = wv[i].z; Bs[k0 + 3][sr] = wv[i].w;
        }
        __syncthreads();

        if (chunk < 3) {
            int kk = (chunk + 1) * 32;
#pragma unroll
            for (int i = 0; i < 4; i++) {
                av[i] = arow_ok
                    ? *reinterpret_cast<const float4*>(hmat + (size_t)(row0 + sr) * H + kk + sc + i * 4)
                    : make_float4(0.f, 0.f, 0.f, 0.f);
                wv[i] = *reinterpret_cast<const float4*>(W + (size_t)sr * H + kk + sc + i * 4);
            }
        }

#pragma unroll 8
        for (int k = 0; k < 32; k++) {
            ulonglong2 b01 = *reinterpret_cast<const ulonglong2*>(&Bs[k][tx * 8]);
            ulonglong2 b23 = *reinterpret_cast<const ulonglong2*>(&Bs[k][tx * 8 + 4]);
            float4 a0 = *reinterpret_cast<const float4*>(&As[k][ty * 8]);
            float4 a1 = *reinterpret_cast<const float4*>(&As[k][ty * 8 + 4]);
            unsigned long long ad[8];
            ad[0] = dup2(a0.x); ad[1] = dup2(a0.y); ad[2] = dup2(a0.z); ad[3] = dup2(a0.w);
            ad[4] = dup2(a1.x); ad[5] = dup2(a1.y); ad[6] = dup2(a1.z); ad[7] = dup2(a1.w);
#pragma unroll
            for (int i = 0; i < 8; i++) {
                acc[i][0] = fma2(ad[i], b01.x, acc[i][0]);
                acc[i][1] = fma2(ad[i], b01.y, acc[i][1]);
                acc[i][2] = fma2(ad[i], b23.x, acc[i][2]);
                acc[i][3] = fma2(ad[i], b23.y, acc[i][3]);
            }
        }
        __syncthreads();
    }

    // epilogue: bias + scale, then per-z store (fp32 perm / fp16 perm / fp16)
    float bl[8];
#pragma unroll
    for (int u = 0; u < 8; u++) bl[u] = __ldg(bias + tx * 8 + u);

#pragma unroll
    for (int i = 0; i < 8; i++) {
        int gr = row0 + ty * 8 + i;
        if (gr >= N) continue;
        float vals[8];
#pragma unroll
        for (int j = 0; j < 4; j++) {
            float lo, hi;
            unpack2(acc[i][j], lo, hi);
            vals[2 * j]     = (lo + bl[2 * j])     * scale;
            vals[2 * j + 1] = (hi + bl[2 * j + 1]) * scale;
        }
        if (z == 0) {
            // Q fp32, permuted: c = tx*8+u -> slot (c&7)*16 + (c>>3) = u*16 + tx
            float* crow = g_Q + (size_t)gr * H;
#pragma unroll
            for (int u = 0; u < 8; u++) crow[u * 16 + tx] = vals[u];
        } else if (z == 1) {
            // K fp16, permuted
            __half* crow = g_K + (size_t)gr * H;
#pragma unroll
            for (int u = 0; u < 8; u++) crow[u * 16 + tx] = __float2half_rn(vals[u]);
        } else {
            // V fp16, original layout: 8 halves = 16B contiguous
            __half hv[8];
#pragma unroll
            for (int u = 0; u < 8; u++) hv[u] = __float2half_rn(vals[u]);
            *reinterpret_cast<uint4*>(g_V + (size_t)gr * H + tx * 8) =
                *reinterpret_cast<const uint4*>(hv);
        }
    }
}

// ---------------- fused sparse attention: one warp per node -----------------
// Q fp32 permuted; K fp16 permuted; V fp16 original.
// Score pass: lane owns slots p=4*lane..4*lane+3 -> head lane>>2 (quad-reduce).
// V pass: lane owns features f=4*lane..4*lane+3 -> head 4*(lane&1)+j,
// attention weights read as float4 (16 LDS.128/node instead of 64 scalar LDS).
__global__ __launch_bounds__(256) void attn_kernel(
    const int* __restrict__ row_ptr,
    const int* __restrict__ col_ind,
    float* __restrict__ out,
    int N)
{
    __shared__ float att[8][NH][MAXDEG];   // [local warp][head][edge]

    const int wl   = threadIdx.x >> 5;
    const int lane = threadIdx.x & 31;
    const int node = blockIdx.x * 8 + wl;
    if (node >= N) return;                 // warp-uniform; only __syncwarp below

    const int start = row_ptr[node];
    int deg = row_ptr[node + 1] - start;
    if (deg > MAXDEG) deg = MAXDEG;

    int colv = 0;
    if (lane < MAXDEG && lane < deg) colv = col_ind[start + lane];

    const float4 q4 = *reinterpret_cast<const float4*>(g_Q + (size_t)node * H + lane * 4);

    const float NEG_INF = __int_as_float(0xff800000);
    float sc[MAXDEG];
#pragma unroll
    for (int e = 0; e < MAXDEG; e++) {
        int col = __shfl_sync(0xffffffffu, colv, e);
        uint2 kr = __ldg(reinterpret_cast<const uint2*>(g_K + (size_t)col * H) + lane);
        float2 k01 = __half22float2(*reinterpret_cast<const __half2*>(&kr.x));
        float2 k23 = __half22float2(*reinterpret_cast<const __half2*>(&kr.y));
        float p = q4.x * k01.x + q4.y * k01.y + q4.z * k23.x + q4.w * k23.y;
        p += __shfl_xor_sync(0xffffffffu, p, 1);
        p += __shfl_xor_sync(0xffffffffu, p, 2);   // quad = 16 d's of head lane>>2
        sc[e] = (e < deg) ? p : NEG_INF;
    }

    // per-lane softmax over edges (all 4 lanes of a quad hold identical copies)
    float m = NEG_INF;
#pragma unroll
    for (int e = 0; e < MAXDEG; e++) m = fmaxf(m, sc[e]);
    float s = 0.0f;
#pragma unroll
    for (int e = 0; e < MAXDEG; e++) { float x = __expf(sc[e] - m); sc[e] = x; s += x; }
    float r = __frcp_rn(s);
#pragma unroll
    for (int e = 0; e < MAXDEG; e++) sc[e] *= r;

    // transpose attn to smem: lane (hd = lane>>2) stores edges e0..e0+3
    {
        int hd = lane >> 2;
        int e0 = (lane & 3) * 4;
        *reinterpret_cast<float4*>(&att[wl][hd][e0]) =
            make_float4(sc[e0], sc[e0 + 1], sc[e0 + 2], sc[e0 + 3]);
    }
    __syncwarp();

    // bspmm: coalesced fp16 V rows; weights as float4 (4 edges per LDS.128)
    const int base = (lane & 1) * 4;
    float4 acc = make_float4(0.f, 0.f, 0.f, 0.f);
#pragma unroll
    for (int e0 = 0; e0 < MAXDEG; e0 += 4) {
        float4 a0 = *reinterpret_cast<const float4*>(&att[wl][base + 0][e0]);
        float4 a1 = *reinterpret_cast<const float4*>(&att[wl][base + 1][e0]);
        float4 a2 = *reinterpret_cast<const float4*>(&att[wl][base + 2][e0]);
        float4 a3 = *reinterpret_cast<const float4*>(&att[wl][base + 3][e0]);
        const float* w0 = reinterpret_cast<const float*>(&a0);
        const float* w1 = reinterpret_cast<const float*>(&a1);
        const float* w2 = reinterpret_cast<const float*>(&a2);
        const float* w3 = reinterpret_cast<const float*>(&a3);
#pragma unroll
        for (int u = 0; u < 4; u++) {
            int col = __shfl_sync(0xffffffffu, colv, e0 + u);
            uint2 vr = __ldg(reinterpret_cast<const uint2*>(g_V + (size_t)col * H) + lane);
            float2 v01 = __half22float2(*reinterpret_cast<const __half2*>(&vr.x));
            float2 v23 = __half22float2(*reinterpret_cast<const __half2*>(&vr.y));
            acc.x += w0[u] * v01.x;
            acc.y += w1[u] * v01.y;
            acc.z += w2[u] * v23.x;
            acc.w += w3[u] * v23.y;
        }
    }
    *reinterpret_cast<float4*>(out + (size_t)node * H + lane * 4) = acc;
}

// ---------------- launch -----------------------------------------------------
extern "C" void kernel_launch(void* const* d_in, const int* in_sizes, int n_in,
                              void* d_out, int out_size) {
    const float* h   = (const float*)d_in[0];
    const float* Wq  = (const float*)d_in[1];
    const float* bq  = (const float*)d_in[2];
    const float* Wk  = (const float*)d_in[3];
    const float* bk  = (const float*)d_in[4];
    const float* Wv  = (const float*)d_in[5];
    const float* bv  = (const float*)d_in[6];
    const int* row_ptr = (const int*)d_in[7];
    const int* col_ind = (const int*)d_in[8];
    float* out = (float*)d_out;

    const int N = in_sizes[0] / H;

    dim3 ggrid((N + 127) / 128, 1, 3);
    qkv_gemm<<<ggrid, 256>>>(h, Wq, bq, Wk, bk, Wv, bv, N);

    const int ablocks = (N + 7) / 8;       // 8 nodes (warps) per 256-thread block
    attn_kernel<<<ablocks, 256>>>(row_ptr, col_ind, out, N);
}